// round 2
// baseline (speedup 1.0000x reference)
#include <cuda_runtime.h>
#include <math.h>

#define B_   32
#define J_   16384
#define D_   32
#define AE_  16
#define H_   128
#define EH_  256
#define IN_DIM_ 49
#define EPS_ 1e-5f

// k_main grid: 296 blocks x 8 warps = 2368 warps, strided over J
#define KB_BLOCKS 296
#define KB_WARPS_PER_BLOCK 8
#define TOT_WARPS (KB_BLOCKS * KB_WARPS_PER_BLOCK)   // 2368

// ---- static device scratch (no allocations allowed) ----
__device__ float g_pre1[J_ * H_];        // 8 MB: per-j layer1 pre-activation (j-only part + hb1)
__device__ float g_sp[J_];               // sum_k pre1[j][k]
__device__ float g_spp[J_];              // sum_k pre1^2
__device__ float g_spw[J_];              // sum_k pre1*w0
__device__ float g_sw0, g_sww;           // sum w0, sum w0^2
__device__ float g_part[TOT_WARPS * B_ * D_];  // ~9.7 MB pooled partials

// ============================================================
// Kernel 0: stats of hW1 column 0 (w0)
// ============================================================
__global__ void k_w0stats(const float* __restrict__ hW1) {
    int k = threadIdx.x;  // 128 threads
    float w = hW1[k];     // hW1[0][k]
    float s = w, ss = w * w;
    #pragma unroll
    for (int o = 16; o; o >>= 1) {
        s  += __shfl_down_sync(0xffffffffu, s,  o);
        ss += __shfl_down_sync(0xffffffffu, ss, o);
    }
    __shared__ float r1[4], r2[4];
    if ((k & 31) == 0) { r1[k >> 5] = s; r2[k >> 5] = ss; }
    __syncthreads();
    if (k == 0) {
        g_sw0 = r1[0] + r1[1] + r1[2] + r1[3];
        g_sww = r2[0] + r2[1] + r2[2] + r2[3];
    }
}

// ============================================================
// Kernel 1: pre1[j][k] = hb1[k] + F_j@hW1[1:33] + E[atse[j]]@hW1[33:49]
// plus per-j LN helper sums. Block = 32 j's, 128 threads (thread = k).
// ============================================================
#define JT_ 32
__global__ __launch_bounds__(128) void k_pre(
    const float* __restrict__ feat_emb,   // [J,32]
    const float* __restrict__ atse_emb,   // [A,16]
    const int*   __restrict__ atse_idx,   // [J]
    const float* __restrict__ hW1,        // [49,128]
    const float* __restrict__ hb1)        // [128]
{
    __shared__ float sfeat[JT_][48];
    __shared__ int   sidx[JT_];
    __shared__ float r1[4], r2[4], r3[4];
    int k = threadIdx.x;
    int jbase = blockIdx.x * JT_;

    if (k < JT_) sidx[k] = atse_idx[jbase + k];
    __syncthreads();
    for (int e = k; e < JT_ * 48; e += 128) {
        int jj = e / 48, i = e % 48;
        sfeat[jj][i] = (i < 32) ? feat_emb[(jbase + jj) * 32 + i]
                                : atse_emb[sidx[jj] * 16 + (i - 32)];
    }
    __syncthreads();

    float wreg[48];
    #pragma unroll
    for (int i = 0; i < 48; i++) wreg[i] = hW1[(1 + i) * H_ + k];
    float w0k = hW1[k];
    float bk  = hb1[k];

    for (int jj = 0; jj < JT_; jj++) {
        float p = bk;
        #pragma unroll
        for (int i = 0; i < 48; i++) p = fmaf(sfeat[jj][i], wreg[i], p);
        g_pre1[(jbase + jj) * H_ + k] = p;

        float s = p, ss = p * p, sw = p * w0k;
        #pragma unroll
        for (int o = 16; o; o >>= 1) {
            s  += __shfl_down_sync(0xffffffffu, s,  o);
            ss += __shfl_down_sync(0xffffffffu, ss, o);
            sw += __shfl_down_sync(0xffffffffu, sw, o);
        }
        if ((k & 31) == 0) { int w = k >> 5; r1[w] = s; r2[w] = ss; r3[w] = sw; }
        __syncthreads();
        if (k == 0) {
            g_sp [jbase + jj] = r1[0] + r1[1] + r1[2] + r1[3];
            g_spp[jbase + jj] = r2[0] + r2[1] + r2[2] + r2[3];
            g_spw[jbase + jj] = r3[0] + r3[1] + r3[2] + r3[3];
        }
        __syncthreads();
    }
}

// ============================================================
// Kernel 2 (hot): per (b,j): LN(closed-form stats) + ReLU ->
// GEMV 128->32 -> LN(32) -> ReLU -> masked pooling (register acc).
// One warp per j, lane = b. Deterministic per-warp partials.
// ============================================================
__global__ __launch_bounds__(256) void k_main(
    const float* __restrict__ x,      // [B,J]
    const int*   __restrict__ mask,   // [B,J]
    const float* __restrict__ hW1,    // [49,128] (row 0 = w0)
    const float* __restrict__ hW2,    // [128,32]
    const float* __restrict__ hb2,    // [32]
    const float* __restrict__ hg1, const float* __restrict__ hB1,  // [128]
    const float* __restrict__ hg2, const float* __restrict__ hB2)  // [32]
{
    __shared__ float sW2[H_ * D_];                 // 16 KB, row-major [k][d]
    __shared__ float sw0[H_], sg1[H_], sB1[H_];
    __shared__ float shb2[D_], sg2[D_], sB2[D_];
    __shared__ float spre[KB_WARPS_PER_BLOCK][H_]; // per-warp pre1 staging

    int t = threadIdx.x;
    for (int e = t; e < H_ * D_; e += 256) sW2[e] = hW2[e];
    if (t < H_) { sw0[t] = hW1[t]; sg1[t] = hg1[t]; sB1[t] = hB1[t]; }
    if (t < D_) { shb2[t] = hb2[t]; sg2[t] = hg2[t]; sB2[t] = hB2[t]; }
    __syncthreads();

    int w = t >> 5, lane = t & 31;
    int wg = blockIdx.x * KB_WARPS_PER_BLOCK + w;
    int b = lane;
    float sw0s = g_sw0, swws = g_sww;

    float acc[D_];
    #pragma unroll
    for (int d = 0; d < D_; d++) acc[d] = 0.f;

    for (int j = wg; j < J_; j += TOT_WARPS) {
        // stage pre1 row (coalesced LDG.128 -> STS.128)
        float4 p4 = ((const float4*)(g_pre1 + j * H_))[lane];
        *((float4*)(spre[w] + lane * 4)) = p4;

        float xb = x[b * J_ + j];
        float sp = g_sp[j], spp = g_spp[j], spw = g_spw[j];
        float mu  = (sp + xb * sw0s) * (1.f / H_);
        float ev2 = fmaf(xb, fmaf(xb, swws, 2.f * spw), spp) * (1.f / H_);
        float var = ev2 - mu * mu;
        float rs  = rsqrtf(var + EPS_);
        __syncwarp();

        float out[D_];
        #pragma unroll
        for (int d = 0; d < D_; d += 4) {
            float4 bb = *((const float4*)(shb2 + d));
            out[d] = bb.x; out[d + 1] = bb.y; out[d + 2] = bb.z; out[d + 3] = bb.w;
        }

        #pragma unroll 2
        for (int m = 0; m < H_ / 4; m++) {
            float4 pr = *((const float4*)(spre[w] + 4 * m));
            float4 wv = *((const float4*)(sw0 + 4 * m));
            float4 gv = *((const float4*)(sg1 + 4 * m));
            float4 bv = *((const float4*)(sB1 + 4 * m));
            float h0 = fmaxf(fmaf(fmaf(xb, wv.x, pr.x) - mu, rs * gv.x, bv.x), 0.f);
            float h1 = fmaxf(fmaf(fmaf(xb, wv.y, pr.y) - mu, rs * gv.y, bv.y), 0.f);
            float h2 = fmaxf(fmaf(fmaf(xb, wv.z, pr.z) - mu, rs * gv.z, bv.z), 0.f);
            float h3 = fmaxf(fmaf(fmaf(xb, wv.w, pr.w) - mu, rs * gv.w, bv.w), 0.f);
            const float* w2r = sW2 + (4 * m) * D_;
            #pragma unroll
            for (int d = 0; d < D_; d += 4) {
                float4 a0 = *((const float4*)(w2r + d));
                float4 a1 = *((const float4*)(w2r + D_ + d));
                float4 a2 = *((const float4*)(w2r + 2 * D_ + d));
                float4 a3 = *((const float4*)(w2r + 3 * D_ + d));
                out[d+0] = fmaf(h0,a0.x, fmaf(h1,a1.x, fmaf(h2,a2.x, fmaf(h3,a3.x, out[d+0]))));
                out[d+1] = fmaf(h0,a0.y, fmaf(h1,a1.y, fmaf(h2,a2.y, fmaf(h3,a3.y, out[d+1]))));
                out[d+2] = fmaf(h0,a0.z, fmaf(h1,a1.z, fmaf(h2,a2.z, fmaf(h3,a3.z, out[d+2]))));
                out[d+3] = fmaf(h0,a0.w, fmaf(h1,a1.w, fmaf(h2,a2.w, fmaf(h3,a3.w, out[d+3]))));
            }
        }

        // second LN over D_=32 (purely per-lane registers)
        float s1 = 0.f, s2 = 0.f;
        #pragma unroll
        for (int d = 0; d < D_; d++) { s1 += out[d]; s2 = fmaf(out[d], out[d], s2); }
        float m2  = s1 * (1.f / D_);
        float v2  = s2 * (1.f / D_) - m2 * m2;
        float rs2 = rsqrtf(v2 + EPS_);
        float mk  = (float)mask[b * J_ + j];

        #pragma unroll
        for (int d = 0; d < D_; d += 4) {
            float4 gg = *((const float4*)(sg2 + d));
            float4 bb = *((const float4*)(sB2 + d));
            float q0 = fmaxf(fmaf((out[d+0] - m2) * rs2, gg.x, bb.x), 0.f);
            float q1 = fmaxf(fmaf((out[d+1] - m2) * rs2, gg.y, bb.y), 0.f);
            float q2 = fmaxf(fmaf((out[d+2] - m2) * rs2, gg.z, bb.z), 0.f);
            float q3 = fmaxf(fmaf((out[d+3] - m2) * rs2, gg.w, bb.w), 0.f);
            acc[d+0] = fmaf(mk, q0, acc[d+0]);
            acc[d+1] = fmaf(mk, q1, acc[d+1]);
            acc[d+2] = fmaf(mk, q2, acc[d+2]);
            acc[d+3] = fmaf(mk, q3, acc[d+3]);
        }
        __syncwarp();  // all lanes done with spre[w] before next overwrite
    }

    float* dst = g_part + (wg * B_ + b) * D_;
    #pragma unroll
    for (int d = 0; d < D_; d += 4) {
        float4 v; v.x = acc[d]; v.y = acc[d+1]; v.z = acc[d+2]; v.w = acc[d+3];
        *((float4*)(dst + d)) = v;
    }
}

// ============================================================
// Kernel 3: reduce partials, mean-pool, encoder MLP, write out.
// One block per b, 256 threads.
// ============================================================
__device__ __forceinline__ float block_reduce256(float v, float* red, int t) {
    red[t] = v; __syncthreads();
    #pragma unroll
    for (int s = 128; s > 0; s >>= 1) {
        if (t < s) red[t] += red[t + s];
        __syncthreads();
    }
    float r = red[0]; __syncthreads();
    return r;
}

__global__ __launch_bounds__(256) void k_final(
    const int*   __restrict__ mask,
    const float* __restrict__ eW1, const float* __restrict__ eb1,
    const float* __restrict__ eg1, const float* __restrict__ eB1,
    const float* __restrict__ eW2, const float* __restrict__ eb2,
    const float* __restrict__ eg2, const float* __restrict__ eB2,
    float* __restrict__ out)
{
    int b = blockIdx.x, t = threadIdx.x;
    __shared__ float red[256];
    __shared__ float sc[D_];
    __shared__ float se[EH_];
    __shared__ float sml[64];
    __shared__ float sgp[8][D_];

    // cnt[b]
    float cm = 0.f;
    for (int j = t; j < J_; j += 256) cm += (float)mask[b * J_ + j];
    float cnt = block_reduce256(cm, red, t);

    // pooled[b][d] = sum over warp partials
    int d = t & 31, g = t >> 5;
    float ps = 0.f;
    for (int w = g; w < TOT_WARPS; w += 8) ps += g_part[(w * B_ + b) * D_ + d];
    sgp[g][d] = ps;
    __syncthreads();
    if (t < D_) {
        float s = 0.f;
        #pragma unroll
        for (int gg = 0; gg < 8; gg++) s += sgp[gg][t];
        sc[t] = s / fmaxf(cnt, 1.f);
    }
    __syncthreads();

    // e = relu(LN(c @ eW1 + eb1)), EH=256 -> one value per thread
    float pe = eb1[t];
    #pragma unroll
    for (int k = 0; k < D_; k++) pe = fmaf(sc[k], eW1[k * EH_ + t], pe);
    float s1 = block_reduce256(pe, red, t);
    float s2 = block_reduce256(pe * pe, red, t);
    float m  = s1 * (1.f / EH_);
    float v  = s2 * (1.f / EH_) - m * m;
    float rs = rsqrtf(v + EPS_);
    se[t] = fmaxf(fmaf((pe - m) * rs, eg1[t], eB1[t]), 0.f);
    __syncthreads();

    // ml = relu(LN(e @ eW2 + eb2)), 64 outputs
    if (t < 64) {
        float pm = eb2[t];
        for (int k = 0; k < EH_; k++) pm = fmaf(se[k], eW2[k * 64 + t], pm);
        sml[t] = pm;
    }
    __syncthreads();
    if (t < 64) {
        float a = 0.f, q = 0.f;
        #pragma unroll
        for (int k = 0; k < 64; k++) { a += sml[k]; q = fmaf(sml[k], sml[k], q); }
        float mm = a * (1.f / 64.f);
        float vv = q * (1.f / 64.f) - mm * mm;
        float rr = rsqrtf(vv + EPS_);
        float ml = fmaxf(fmaf((sml[t] - mm) * rr, eg2[t], eB2[t]), 0.f);
        // output = concat(mu.flatten(), logvar.flatten()) -> [2][B][32]
        int off = (t < 32) ? (b * 32 + t) : (B_ * 32 + b * 32 + (t - 32));
        out[off] = ml;
    }
}

// ============================================================
extern "C" void kernel_launch(void* const* d_in, const int* in_sizes, int n_in,
                              void* d_out, int out_size) {
    const float* x         = (const float*)d_in[0];
    const int*   mask      = (const int*)  d_in[1];
    const int*   atse_idx  = (const int*)  d_in[2];
    const float* feat_emb  = (const float*)d_in[3];
    const float* atse_emb  = (const float*)d_in[4];
    const float* hW1       = (const float*)d_in[5];
    const float* hb1       = (const float*)d_in[6];
    const float* hg1       = (const float*)d_in[7];
    const float* hB1       = (const float*)d_in[8];
    const float* hW2       = (const float*)d_in[9];
    const float* hb2       = (const float*)d_in[10];
    const float* hg2       = (const float*)d_in[11];
    const float* hB2       = (const float*)d_in[12];
    const float* eW1       = (const float*)d_in[13];
    const float* eb1       = (const float*)d_in[14];
    const float* eg1       = (const float*)d_in[15];
    const float* eB1       = (const float*)d_in[16];
    const float* eW2       = (const float*)d_in[17];
    const float* eb2       = (const float*)d_in[18];
    const float* eg2       = (const float*)d_in[19];
    const float* eB2       = (const float*)d_in[20];
    float* out = (float*)d_out;

    k_w0stats<<<1, 128>>>(hW1);
    k_pre<<<J_ / JT_, 128>>>(feat_emb, atse_emb, atse_idx, hW1, hb1);
    k_main<<<KB_BLOCKS, 256>>>(x, mask, hW1, hW2, hb2, hg1, hB1, hg2, hB2);
    k_final<<<B_, 256>>>(mask, eW1, eb1, eg1, eB1, eW2, eb2, eg2, eB2, out);
}

// round 4
// speedup vs baseline: 1.1492x; 1.1492x over previous
#include <cuda_runtime.h>
#include <math.h>

#define B_   32
#define J_   16384
#define D_   32
#define AE_  16
#define H_   128
#define EH_  256
#define EPS_ 1e-5f

#define KB_BLOCKS 296
#define KB_WARPS_PER_BLOCK 8
#define TOT_WARPS (KB_BLOCKS * KB_WARPS_PER_BLOCK)   // 2368

typedef unsigned long long ull;

// ---- static device scratch ----
__device__ float g_pre1[J_ * H_];                // per-j layer1 pre-activation
__device__ float g_sp[J_], g_spp[J_], g_spw[J_]; // closed-form LN helper sums
__device__ float g_sw0, g_sww;
__device__ float g_part[KB_BLOCKS * B_ * D_];    // per-BLOCK pooled partials
__device__ float g_cnt[KB_BLOCKS * B_];          // per-BLOCK mask counts
__device__ float g_xT[J_ * B_];                  // transposed x   [J][B]
__device__ float g_mT[J_ * B_];                  // transposed mask (as float) [J][B]

// ---- packed f32x2 helpers (bit-exact fp32 pairs, FFMA2 in SASS) ----
__device__ __forceinline__ ull ffma2(ull a, ull b, ull c) {
    ull d; asm("fma.rn.f32x2 %0, %1, %2, %3;" : "=l"(d) : "l"(a), "l"(b), "l"(c)); return d;
}
__device__ __forceinline__ ull add2(ull a, ull b) {
    ull d; asm("add.rn.f32x2 %0, %1, %2;" : "=l"(d) : "l"(a), "l"(b)); return d;
}
__device__ __forceinline__ ull mul2(ull a, ull b) {
    ull d; asm("mul.rn.f32x2 %0, %1, %2;" : "=l"(d) : "l"(a), "l"(b)); return d;
}
__device__ __forceinline__ ull pack2(float v) {
    ull r; asm("mov.b64 %0, {%1, %1};" : "=l"(r) : "f"(v)); return r;
}
#define UNPK(lo, hi, v) asm("mov.b64 {%0, %1}, %2;" : "=f"(lo), "=f"(hi) : "l"(v))

// ============================================================
// Kernel 0: stats of hW1 column 0 (w0)
// ============================================================
__global__ void k_w0stats(const float* __restrict__ hW1) {
    int k = threadIdx.x;  // 128 threads
    float w = hW1[k];
    float s = w, ss = w * w;
    #pragma unroll
    for (int o = 16; o; o >>= 1) {
        s  += __shfl_down_sync(0xffffffffu, s,  o);
        ss += __shfl_down_sync(0xffffffffu, ss, o);
    }
    __shared__ float r1[4], r2[4];
    if ((k & 31) == 0) { r1[k >> 5] = s; r2[k >> 5] = ss; }
    __syncthreads();
    if (k == 0) {
        g_sw0 = r1[0] + r1[1] + r1[2] + r1[3];
        g_sww = r2[0] + r2[1] + r2[2] + r2[3];
    }
}

// ============================================================
// Kernel 0b: transpose x and mask into [J][B] (coalesced hot-loop loads)
// Block: 256 threads handles a 32j x 32b tile.
// ============================================================
__global__ __launch_bounds__(256) void k_xpose(
    const float* __restrict__ x, const int* __restrict__ mask)
{
    __shared__ float tx[32][33];
    __shared__ float tm[32][33];
    int jbase = blockIdx.x * 32;
    int t = threadIdx.x;
    // read coalesced along j: thread -> (b_row = t/32*? ) 256 threads: 8 rows of b at a time
    #pragma unroll
    for (int r = 0; r < 4; r++) {
        int b  = (t >> 5) + r * 8;     // 0..31
        int jj = t & 31;
        tx[b][jj] = x[b * J_ + jbase + jj];
        tm[b][jj] = (float)mask[b * J_ + jbase + jj];
    }
    __syncthreads();
    // write coalesced along b
    #pragma unroll
    for (int r = 0; r < 4; r++) {
        int jj = (t >> 5) + r * 8;
        int b  = t & 31;
        g_xT[(jbase + jj) * B_ + b] = tx[b][jj];
        g_mT[(jbase + jj) * B_ + b] = tm[b][jj];
    }
}

// ============================================================
// Kernel 1: pre1[j][k] + per-j LN helper sums.
// ============================================================
#define JT_ 32
__global__ __launch_bounds__(128) void k_pre(
    const float* __restrict__ feat_emb, const float* __restrict__ atse_emb,
    const int* __restrict__ atse_idx, const float* __restrict__ hW1,
    const float* __restrict__ hb1)
{
    __shared__ float sfeat[JT_][48];
    __shared__ int   sidx[JT_];
    __shared__ float r1[4], r2[4], r3[4];
    int k = threadIdx.x;
    int jbase = blockIdx.x * JT_;

    if (k < JT_) sidx[k] = atse_idx[jbase + k];
    __syncthreads();
    for (int e = k; e < JT_ * 48; e += 128) {
        int jj = e / 48, i = e % 48;
        sfeat[jj][i] = (i < 32) ? feat_emb[(jbase + jj) * 32 + i]
                                : atse_emb[sidx[jj] * 16 + (i - 32)];
    }
    __syncthreads();

    float wreg[48];
    #pragma unroll
    for (int i = 0; i < 48; i++) wreg[i] = hW1[(1 + i) * H_ + k];
    float w0k = hW1[k];
    float bk  = hb1[k];

    for (int jj = 0; jj < JT_; jj++) {
        float p = bk;
        #pragma unroll
        for (int i = 0; i < 48; i++) p = fmaf(sfeat[jj][i], wreg[i], p);
        g_pre1[(jbase + jj) * H_ + k] = p;

        float s = p, ss = p * p, sw = p * w0k;
        #pragma unroll
        for (int o = 16; o; o >>= 1) {
            s  += __shfl_down_sync(0xffffffffu, s,  o);
            ss += __shfl_down_sync(0xffffffffu, ss, o);
            sw += __shfl_down_sync(0xffffffffu, sw, o);
        }
        if ((k & 31) == 0) { int w = k >> 5; r1[w] = s; r2[w] = ss; r3[w] = sw; }
        __syncthreads();
        if (k == 0) {
            g_sp [jbase + jj] = r1[0] + r1[1] + r1[2] + r1[3];
            g_spp[jbase + jj] = r2[0] + r2[1] + r2[2] + r2[3];
            g_spw[jbase + jj] = r3[0] + r3[1] + r3[2] + r3[3];
        }
        __syncthreads();
    }
}

// ============================================================
// Kernel 2 (hot): f32x2-packed LN+GEMV+LN+pool. One warp per j, lane = b.
// ============================================================
__global__ __launch_bounds__(256) void k_main(
    const float* __restrict__ hW1, const float* __restrict__ hW2,
    const float* __restrict__ hb2,
    const float* __restrict__ hg1, const float* __restrict__ hB1,
    const float* __restrict__ hg2, const float* __restrict__ hB2)
{
    __shared__ __align__(16) float sW2[H_ * D_];                 // 16 KB [k][d]
    __shared__ __align__(16) float sw0[H_], sg1[H_], sB1[H_];
    __shared__ __align__(16) float shb2[D_], sg2[D_], sB2[D_];
    __shared__ __align__(16) float spre[KB_WARPS_PER_BLOCK][H_]; // 4 KB
    __shared__ __align__(16) float sred[4][B_][D_ + 1];          // ~16.9 KB
    __shared__ float scnt[KB_WARPS_PER_BLOCK][B_];

    int t = threadIdx.x;
    for (int e = t; e < H_ * D_; e += 256) sW2[e] = hW2[e];
    if (t < H_) { sw0[t] = hW1[t]; sg1[t] = hg1[t]; sB1[t] = hB1[t]; }
    if (t < D_) { shb2[t] = hb2[t]; sg2[t] = hg2[t]; sB2[t] = hB2[t]; }
    __syncthreads();

    int w = t >> 5, lane = t & 31;
    int wg = blockIdx.x * KB_WARPS_PER_BLOCK + w;
    float sw0s = g_sw0, swws = g_sww;

    float acc[D_];
    #pragma unroll
    for (int d = 0; d < D_; d++) acc[d] = 0.f;
    float cacc = 0.f;

    for (int j = wg; j < J_; j += TOT_WARPS) {
        // stage pre1 row (coalesced LDG.128 -> STS.128)
        float4 p4 = ((const float4*)(g_pre1 + j * H_))[lane];
        *((float4*)(spre[w] + lane * 4)) = p4;

        float xb = g_xT[j * B_ + lane];          // coalesced
        float sp = g_sp[j], spp = g_spp[j], spw = g_spw[j];
        float mu  = (sp + xb * sw0s) * (1.f / H_);
        float ev2 = fmaf(xb, fmaf(xb, swws, 2.f * spw), spp) * (1.f / H_);
        float rs  = rsqrtf(ev2 - mu * mu + EPS_);
        ull xb2  = pack2(xb);
        ull nmu2 = pack2(-mu);
        ull rs2p = pack2(rs);
        __syncwarp();

        // init ALL 16 packed accumulators with hb2 (32 floats = 8 ulonglong2)
        ull o[16];
        #pragma unroll
        for (int q4 = 0; q4 < 8; q4++) {
            ulonglong2 v = ((const ulonglong2*)shb2)[q4 >> 1];
            // q4 even -> v.x/v.y pair handled below; simpler: direct 64-bit loads
            o[q4] = ((const ull*)shb2)[q4];
            o[q4 + 8] = ((const ull*)shb2)[q4 + 8];
        }

        #pragma unroll 4
        for (int m = 0; m < H_ / 4; m++) {
            ulonglong2 pr = *((const ulonglong2*)(spre[w] + 4 * m));
            ulonglong2 wv = *((const ulonglong2*)(sw0 + 4 * m));
            ulonglong2 gv = *((const ulonglong2*)(sg1 + 4 * m));
            ulonglong2 bv = *((const ulonglong2*)(sB1 + 4 * m));
            ull t01 = ffma2(xb2, wv.x, pr.x);
            ull t23 = ffma2(xb2, wv.y, pr.y);
            ull u01 = add2(t01, nmu2);
            ull u23 = add2(t23, nmu2);
            ull rg01 = mul2(rs2p, gv.x);
            ull rg23 = mul2(rs2p, gv.y);
            ull h01 = ffma2(u01, rg01, bv.x);
            ull h23 = ffma2(u23, rg23, bv.y);
            float h0, h1, h2, h3;
            UNPK(h0, h1, h01); UNPK(h2, h3, h23);
            h0 = fmaxf(h0, 0.f); h1 = fmaxf(h1, 0.f);
            h2 = fmaxf(h2, 0.f); h3 = fmaxf(h3, 0.f);
            ull hp0 = pack2(h0), hp1 = pack2(h1), hp2 = pack2(h2), hp3 = pack2(h3);

            const ulonglong2* w2r = (const ulonglong2*)(sW2 + (4 * m) * D_); // 8/row
            #pragma unroll
            for (int q = 0; q < 8; q++) {
                ulonglong2 a0 = w2r[q];
                ulonglong2 a1 = w2r[8 + q];
                ulonglong2 a2 = w2r[16 + q];
                ulonglong2 a3 = w2r[24 + q];
                o[2*q]   = ffma2(hp0, a0.x, ffma2(hp1, a1.x, ffma2(hp2, a2.x, ffma2(hp3, a3.x, o[2*q]))));
                o[2*q+1] = ffma2(hp0, a0.y, ffma2(hp1, a1.y, ffma2(hp2, a2.y, ffma2(hp3, a3.y, o[2*q+1]))));
            }
        }

        float out[D_];
        #pragma unroll
        for (int q = 0; q < 16; q++) UNPK(out[2 * q], out[2 * q + 1], o[q]);

        float s1 = 0.f, s2 = 0.f;
        #pragma unroll
        for (int d = 0; d < D_; d++) { s1 += out[d]; s2 = fmaf(out[d], out[d], s2); }
        float m2  = s1 * (1.f / D_);
        float v2  = s2 * (1.f / D_) - m2 * m2;
        float rs2 = rsqrtf(v2 + EPS_);
        float mk  = g_mT[j * B_ + lane];          // coalesced
        cacc += mk;

        #pragma unroll
        for (int d = 0; d < D_; d += 4) {
            float4 gg = *((const float4*)(sg2 + d));
            float4 bb = *((const float4*)(sB2 + d));
            float q0 = fmaxf(fmaf((out[d+0] - m2) * rs2, gg.x, bb.x), 0.f);
            float q1 = fmaxf(fmaf((out[d+1] - m2) * rs2, gg.y, bb.y), 0.f);
            float q2 = fmaxf(fmaf((out[d+2] - m2) * rs2, gg.z, bb.z), 0.f);
            float q3 = fmaxf(fmaf((out[d+3] - m2) * rs2, gg.w, bb.w), 0.f);
            acc[d+0] = fmaf(mk, q0, acc[d+0]);
            acc[d+1] = fmaf(mk, q1, acc[d+1]);
            acc[d+2] = fmaf(mk, q2, acc[d+2]);
            acc[d+3] = fmaf(mk, q3, acc[d+3]);
        }
        __syncwarp();
    }

    // ---- block-level tree reduction of acc (8 warps -> 1), deterministic ----
    #pragma unroll
    for (int half = 4; half >= 1; half >>= 1) {
        if (w >= half && w < 2 * half) {
            float* dst = &sred[w - half][lane][0];
            #pragma unroll
            for (int d = 0; d < D_; d++) dst[d] = acc[d];
        }
        __syncthreads();
        if (w < half) {
            const float* src = &sred[w][lane][0];
            #pragma unroll
            for (int d = 0; d < D_; d++) acc[d] += src[d];
        }
        __syncthreads();
    }

    scnt[w][lane] = cacc;
    __syncthreads();

    if (w == 0) {
        float* dst = g_part + blockIdx.x * (B_ * D_) + lane * D_;
        #pragma unroll
        for (int d = 0; d < D_; d += 4) {
            float4 v; v.x = acc[d]; v.y = acc[d+1]; v.z = acc[d+2]; v.w = acc[d+3];
            *((float4*)(dst + d)) = v;
        }
        float c = 0.f;
        #pragma unroll
        for (int i = 0; i < KB_WARPS_PER_BLOCK; i++) c += scnt[i][lane];
        g_cnt[blockIdx.x * B_ + lane] = c;
    }
}

// ============================================================
// Kernel 3: reduce block partials, mean-pool, encoder MLP, write out.
// ============================================================
__device__ __forceinline__ float block_reduce256(float v, float* red, int t) {
    red[t] = v; __syncthreads();
    #pragma unroll
    for (int s = 128; s > 0; s >>= 1) {
        if (t < s) red[t] += red[t + s];
        __syncthreads();
    }
    float r = red[0]; __syncthreads();
    return r;
}

__global__ __launch_bounds__(256) void k_final(
    const float* __restrict__ eW1, const float* __restrict__ eb1,
    const float* __restrict__ eg1, const float* __restrict__ eB1,
    const float* __restrict__ eW2, const float* __restrict__ eb2,
    const float* __restrict__ eg2, const float* __restrict__ eB2,
    float* __restrict__ out)
{
    int b = blockIdx.x, t = threadIdx.x;
    __shared__ float red[256];
    __shared__ float sc[D_];
    __shared__ float se[EH_];
    __shared__ float sml[64];
    __shared__ float sgp[8][D_];

    float cm = 0.f;
    for (int blk = t; blk < KB_BLOCKS; blk += 256) cm += g_cnt[blk * B_ + b];
    float cnt = block_reduce256(cm, red, t);

    int d = t & 31, g = t >> 5;
    float ps = 0.f;
    for (int blk = g; blk < KB_BLOCKS; blk += 8) ps += g_part[blk * (B_ * D_) + b * D_ + d];
    sgp[g][d] = ps;
    __syncthreads();
    if (t < D_) {
        float s = 0.f;
        #pragma unroll
        for (int gg = 0; gg < 8; gg++) s += sgp[gg][t];
        sc[t] = s / fmaxf(cnt, 1.f);
    }
    __syncthreads();

    float pe = eb1[t];
    #pragma unroll
    for (int k = 0; k < D_; k++) pe = fmaf(sc[k], eW1[k * EH_ + t], pe);
    float s1 = block_reduce256(pe, red, t);
    float s2 = block_reduce256(pe * pe, red, t);
    float m  = s1 * (1.f / EH_);
    float v  = s2 * (1.f / EH_) - m * m;
    float rs = rsqrtf(v + EPS_);
    se[t] = fmaxf(fmaf((pe - m) * rs, eg1[t], eB1[t]), 0.f);
    __syncthreads();

    if (t < 64) {
        float pm = eb2[t];
        for (int k = 0; k < EH_; k++) pm = fmaf(se[k], eW2[k * 64 + t], pm);
        sml[t] = pm;
    }
    __syncthreads();
    if (t < 64) {
        float a = 0.f, q = 0.f;
        #pragma unroll
        for (int k = 0; k < 64; k++) { a += sml[k]; q = fmaf(sml[k], sml[k], q); }
        float mm = a * (1.f / 64.f);
        float vv = q * (1.f / 64.f) - mm * mm;
        float rr = rsqrtf(vv + EPS_);
        float ml = fmaxf(fmaf((sml[t] - mm) * rr, eg2[t], eB2[t]), 0.f);
        int off = (t < 32) ? (b * 32 + t) : (B_ * 32 + b * 32 + (t - 32));
        out[off] = ml;
    }
}

// ============================================================
extern "C" void kernel_launch(void* const* d_in, const int* in_sizes, int n_in,
                              void* d_out, int out_size) {
    const float* x         = (const float*)d_in[0];
    const int*   mask      = (const int*)  d_in[1];
    const int*   atse_idx  = (const int*)  d_in[2];
    const float* feat_emb  = (const float*)d_in[3];
    const float* atse_emb  = (const float*)d_in[4];
    const float* hW1       = (const float*)d_in[5];
    const float* hb1       = (const float*)d_in[6];
    const float* hg1       = (const float*)d_in[7];
    const float* hB1       = (const float*)d_in[8];
    const float* hW2       = (const float*)d_in[9];
    const float* hb2       = (const float*)d_in[10];
    const float* hg2       = (const float*)d_in[11];
    const float* hB2       = (const float*)d_in[12];
    const float* eW1       = (const float*)d_in[13];
    const float* eb1       = (const float*)d_in[14];
    const float* eg1       = (const float*)d_in[15];
    const float* eB1       = (const float*)d_in[16];
    const float* eW2       = (const float*)d_in[17];
    const float* eb2       = (const float*)d_in[18];
    const float* eg2       = (const float*)d_in[19];
    const float* eB2       = (const float*)d_in[20];
    float* out = (float*)d_out;

    k_w0stats<<<1, 128>>>(hW1);
    k_xpose<<<J_ / 32, 256>>>(x, mask);
    k_pre<<<J_ / JT_, 128>>>(feat_emb, atse_emb, atse_idx, hW1, hb1);
    k_main<<<KB_BLOCKS, 256>>>(hW1, hW2, hb2, hg1, hB1, hg2, hB2);
    k_final<<<B_, 256>>>(eW1, eb1, eg1, eB1, eW2, eb2, eg2, eB2, out);
}

// round 5
// speedup vs baseline: 1.6010x; 1.3932x over previous
#include <cuda_runtime.h>
#include <math.h>

#define B_   32
#define J_   16384
#define D_   32
#define H_   128
#define EH_  256
#define EPS_ 1e-5f

#define KB_BLOCKS 296
#define KB_WARPS  8
#define TOT_WARPS (KB_BLOCKS * KB_WARPS)   // 2368
#define NPAIR (J_ / 2)                     // 8192

typedef unsigned long long ull;

// ---- static device scratch ----
__device__ float g_pre1[J_ * H_];        // precg[j][k] = (pre - sp/H) * g1[k]
__device__ float g_sppc[J_], g_spwc[J_]; // sum prec^2, sum prec*w0c
__device__ float g_w0c[H_];              // centered w0
__device__ ull   g_wb[H_];               // interleaved pairs: [2p]=(wcg_{2p},wcg_{2p+1}) [2p+1]=(B1_{2p},B1_{2p+1})
__device__ float g_swwc;                 // sum w0c^2
__device__ float g_part[KB_BLOCKS * B_ * D_];
__device__ float g_cnt[KB_BLOCKS * B_];
__device__ float g_xT[J_ * B_];
__device__ float g_mT[J_ * B_];

// ---- packed f32x2 helpers ----
__device__ __forceinline__ ull ffma2(ull a, ull b, ull c) {
    ull d; asm("fma.rn.f32x2 %0, %1, %2, %3;" : "=l"(d) : "l"(a), "l"(b), "l"(c)); return d;
}
__device__ __forceinline__ ull pack2(float v) {
    ull r; asm("mov.b64 %0, {%1, %1};" : "=l"(r) : "f"(v)); return r;
}
__device__ __forceinline__ ull packf(float a, float b) {
    ull r; asm("mov.b64 %0, {%1, %2};" : "=l"(r) : "f"(a), "f"(b)); return r;
}
#define UNPK(lo, hi, v) asm("mov.b64 {%0, %1}, %2;" : "=f"(lo), "=f"(hi) : "l"(v))

// ============================================================
// Kernel 0: centered w0, interleaved (w0cg,B1) table, sum w0c^2
// ============================================================
__global__ void k_prep0(const float* __restrict__ hW1,
                        const float* __restrict__ hg1,
                        const float* __restrict__ hB1) {
    __shared__ float sred[4];
    __shared__ float s_sw0;
    __shared__ float swcg[H_], sB[H_];
    int k = threadIdx.x;  // 128
    float w = hW1[k];
    float s = w;
    #pragma unroll
    for (int o = 16; o; o >>= 1) s += __shfl_down_sync(0xffffffffu, s, o);
    if ((k & 31) == 0) sred[k >> 5] = s;
    __syncthreads();
    if (k == 0) s_sw0 = sred[0] + sred[1] + sred[2] + sred[3];
    __syncthreads();
    float w0c = w - s_sw0 * (1.f / H_);
    g_w0c[k] = w0c;
    swcg[k] = w0c * hg1[k];
    sB[k]   = hB1[k];
    float ss = w0c * w0c;
    #pragma unroll
    for (int o = 16; o; o >>= 1) ss += __shfl_down_sync(0xffffffffu, ss, o);
    __syncthreads();
    if ((k & 31) == 0) sred[k >> 5] = ss;
    __syncthreads();
    if (k == 0) g_swwc = sred[0] + sred[1] + sred[2] + sred[3];
    if (k < 64) {
        g_wb[2 * k]     = packf(swcg[2 * k], swcg[2 * k + 1]);
        g_wb[2 * k + 1] = packf(sB[2 * k], sB[2 * k + 1]);
    }
}

// ============================================================
// Kernel 0b: transpose x and mask into [J][B]
// ============================================================
__global__ __launch_bounds__(256) void k_xpose(
    const float* __restrict__ x, const int* __restrict__ mask)
{
    __shared__ float tx[32][33];
    __shared__ float tm[32][33];
    int jbase = blockIdx.x * 32;
    int t = threadIdx.x;
    #pragma unroll
    for (int r = 0; r < 4; r++) {
        int b  = (t >> 5) + r * 8;
        int jj = t & 31;
        tx[b][jj] = x[b * J_ + jbase + jj];
        tm[b][jj] = (float)mask[b * J_ + jbase + jj];
    }
    __syncthreads();
    #pragma unroll
    for (int r = 0; r < 4; r++) {
        int jj = (t >> 5) + r * 8;
        int b  = t & 31;
        g_xT[(jbase + jj) * B_ + b] = tx[b][jj];
        g_mT[(jbase + jj) * B_ + b] = tm[b][jj];
    }
}

// ============================================================
// Kernel 1: precg[j][k] + per-j centered LN helper sums.
// Pass 1 (thread=k): p = hb1 + feats@W1 (FFMA2 along input pairs) -> smem
// Pass 2 (warp per j): sp reduce -> prec -> precg store + spp/spw reduce
// ============================================================
__global__ __launch_bounds__(128) void k_pre(
    const float* __restrict__ feat_emb, const float* __restrict__ atse_emb,
    const int* __restrict__ atse_idx, const float* __restrict__ hW1,
    const float* __restrict__ hb1, const float* __restrict__ hg1)
{
    __shared__ __align__(16) float sfeat[32][48];
    __shared__ int sidx[32];
    __shared__ __align__(16) float sP[32][H_];
    int k = threadIdx.x;
    int jbase = blockIdx.x * 32;

    if (k < 32) sidx[k] = atse_idx[jbase + k];
    __syncthreads();
    for (int e = k; e < 32 * 48; e += 128) {
        int jj = e / 48, i = e % 48;
        sfeat[jj][i] = (i < 32) ? feat_emb[(jbase + jj) * 32 + i]
                                : atse_emb[sidx[jj] * 16 + (i - 32)];
    }

    ull wp[24];
    #pragma unroll
    for (int ip = 0; ip < 24; ip++)
        wp[ip] = packf(hW1[(1 + 2 * ip) * H_ + k], hW1[(2 + 2 * ip) * H_ + k]);
    float bk = hb1[k];
    __syncthreads();

    for (int jj = 0; jj < 32; jj++) {
        ull acc = packf(bk, 0.f);
        #pragma unroll
        for (int ip = 0; ip < 24; ip++) {
            ull f = *(const ull*)&sfeat[jj][2 * ip];
            acc = ffma2(f, wp[ip], acc);
        }
        float lo, hi; UNPK(lo, hi, acc);
        sP[jj][k] = lo + hi;
    }
    __syncthreads();

    int w = k >> 5, lane = k & 31;
    #pragma unroll
    for (int r = 0; r < 8; r++) {
        int jj = w + 4 * r;
        int j = jbase + jj;
        float4 p4 = *(const float4*)&sP[jj][lane * 4];
        float sp = p4.x + p4.y + p4.z + p4.w;
        #pragma unroll
        for (int o = 16; o; o >>= 1) sp += __shfl_xor_sync(0xffffffffu, sp, o);
        float mval = sp * (1.f / H_);
        float c0 = p4.x - mval, c1 = p4.y - mval, c2 = p4.z - mval, c3 = p4.w - mval;
        float4 w4 = *(const float4*)&g_w0c[lane * 4];
        float4 g4 = *(const float4*)&hg1[lane * 4];
        float4 pg; pg.x = c0 * g4.x; pg.y = c1 * g4.y; pg.z = c2 * g4.z; pg.w = c3 * g4.w;
        *(float4*)&g_pre1[j * H_ + lane * 4] = pg;
        float ss = c0 * c0 + c1 * c1 + c2 * c2 + c3 * c3;
        float sw = c0 * w4.x + c1 * w4.y + c2 * w4.z + c3 * w4.w;
        #pragma unroll
        for (int o = 16; o; o >>= 1) {
            ss += __shfl_xor_sync(0xffffffffu, ss, o);
            sw += __shfl_xor_sync(0xffffffffu, sw, o);
        }
        if (lane == 0) { g_sppc[j] = ss; g_spwc[j] = sw; }
    }
}

// ============================================================
// Kernel 2 (hot): JTILE=2. One warp per j-PAIR, lane = b.
// h = relu((x*w0cg + precg)*rs + B1); GEMV 128->32 packed; LN2; pool.
// ============================================================
__global__ __launch_bounds__(256, 2) void k_main(
    const float* __restrict__ hW2, const float* __restrict__ hb2,
    const float* __restrict__ hg2, const float* __restrict__ hB2)
{
    __shared__ __align__(16) float sW2[H_ * D_];                  // 16 KB [k][d]
    __shared__ __align__(16) ull   swb[H_];                       // 1 KB
    __shared__ __align__(16) float shb2[D_], sg2[D_], sB2[D_];
    __shared__ __align__(16) float spre[KB_WARPS][2][H_];         // 8 KB
    __shared__ __align__(16) float sred[4][B_][D_ + 1];           // ~16.9 KB
    __shared__ float scnt[KB_WARPS][B_];

    int t = threadIdx.x;
    for (int e = t; e < H_ * D_; e += 256) sW2[e] = hW2[e];
    if (t < H_) swb[t] = g_wb[t];
    if (t < D_) { shb2[t] = hb2[t]; sg2[t] = hg2[t]; sB2[t] = hB2[t]; }
    __syncthreads();

    int w = t >> 5, lane = t & 31;
    int wg = blockIdx.x * KB_WARPS + w;
    float swwc = g_swwc;

    float acc[D_];
    #pragma unroll
    for (int d = 0; d < D_; d++) acc[d] = 0.f;
    float cacc = 0.f;

    for (int jp = wg; jp < NPAIR; jp += TOT_WARPS) {
        int j0 = 2 * jp, j1 = 2 * jp + 1;
        // stage precg rows (coalesced)
        float4 q0 = ((const float4*)(g_pre1 + j0 * H_))[lane];
        float4 q1 = ((const float4*)(g_pre1 + j1 * H_))[lane];
        *((float4*)(spre[w][0] + lane * 4)) = q0;
        *((float4*)(spre[w][1] + lane * 4)) = q1;

        float xb0 = g_xT[j0 * B_ + lane];
        float xb1 = g_xT[j1 * B_ + lane];
        float sppc0 = g_sppc[j0], spwc0 = g_spwc[j0];
        float sppc1 = g_sppc[j1], spwc1 = g_spwc[j1];
        float ev0 = fmaf(xb0, fmaf(xb0, swwc, 2.f * spwc0), sppc0) * (1.f / H_);
        float ev1 = fmaf(xb1, fmaf(xb1, swwc, 2.f * spwc1), sppc1) * (1.f / H_);
        float rs0 = rsqrtf(ev0 + EPS_);
        float rs1 = rsqrtf(ev1 + EPS_);
        ull xb2_0 = pack2(xb0), xb2_1 = pack2(xb1);
        ull rs2_0 = pack2(rs0), rs2_1 = pack2(rs1);
        __syncwarp();

        ull o0[16], o1[16];
        #pragma unroll
        for (int q = 0; q < 8; q++) {
            ulonglong2 v = ((const ulonglong2*)shb2)[q >> 1];
            (void)v;
            o0[q]     = ((const ull*)shb2)[q];
            o0[q + 8] = ((const ull*)shb2)[q + 8];
            o1[q]     = o0[q];
            o1[q + 8] = o0[q + 8];
        }

        const ulonglong2* swb2 = (const ulonglong2*)swb;
        #pragma unroll 2
        for (int m = 0; m < H_ / 4; m++) {
            ulonglong2 cA = swb2[2 * m];       // (wc01, B01)
            ulonglong2 cB = swb2[2 * m + 1];   // (wc23, B23)
            ulonglong2 pr0 = *((const ulonglong2*)(spre[w][0] + 4 * m));
            ulonglong2 pr1 = *((const ulonglong2*)(spre[w][1] + 4 * m));

            ull h01a = ffma2(ffma2(xb2_0, cA.x, pr0.x), rs2_0, cA.y);
            ull h23a = ffma2(ffma2(xb2_0, cB.x, pr0.y), rs2_0, cB.y);
            ull h01b = ffma2(ffma2(xb2_1, cA.x, pr1.x), rs2_1, cA.y);
            ull h23b = ffma2(ffma2(xb2_1, cB.x, pr1.y), rs2_1, cB.y);
            float f0, f1, f2, f3, e0, e1, e2, e3;
            UNPK(f0, f1, h01a); UNPK(f2, f3, h23a);
            UNPK(e0, e1, h01b); UNPK(e2, e3, h23b);
            f0 = fmaxf(f0, 0.f); f1 = fmaxf(f1, 0.f); f2 = fmaxf(f2, 0.f); f3 = fmaxf(f3, 0.f);
            e0 = fmaxf(e0, 0.f); e1 = fmaxf(e1, 0.f); e2 = fmaxf(e2, 0.f); e3 = fmaxf(e3, 0.f);
            ull hp00 = pack2(f0), hp01 = pack2(f1), hp02 = pack2(f2), hp03 = pack2(f3);
            ull hp10 = pack2(e0), hp11 = pack2(e1), hp12 = pack2(e2), hp13 = pack2(e3);

            const ulonglong2* w2r = (const ulonglong2*)(sW2 + (4 * m) * D_);
            #pragma unroll
            for (int q = 0; q < 8; q++) {
                ulonglong2 a0 = w2r[q];
                ulonglong2 a1 = w2r[8 + q];
                ull t0x = ffma2(hp00, a0.x, ffma2(hp01, a1.x, o0[2 * q]));
                ull t0y = ffma2(hp00, a0.y, ffma2(hp01, a1.y, o0[2 * q + 1]));
                ull t1x = ffma2(hp10, a0.x, ffma2(hp11, a1.x, o1[2 * q]));
                ull t1y = ffma2(hp10, a0.y, ffma2(hp11, a1.y, o1[2 * q + 1]));
                ulonglong2 a2 = w2r[16 + q];
                ulonglong2 a3 = w2r[24 + q];
                o0[2 * q]     = ffma2(hp02, a2.x, ffma2(hp03, a3.x, t0x));
                o0[2 * q + 1] = ffma2(hp02, a2.y, ffma2(hp03, a3.y, t0y));
                o1[2 * q]     = ffma2(hp12, a2.x, ffma2(hp13, a3.x, t1x));
                o1[2 * q + 1] = ffma2(hp12, a2.y, ffma2(hp13, a3.y, t1y));
            }
        }

        // ---- LN2 + pool, j0 then j1 ----
        #pragma unroll
        for (int jj = 0; jj < 2; jj++) {
            ull* op = jj ? o1 : o0;
            float out[D_];
            #pragma unroll
            for (int q = 0; q < 16; q++) UNPK(out[2 * q], out[2 * q + 1], op[q]);
            float s1 = 0.f, s2 = 0.f;
            #pragma unroll
            for (int d = 0; d < D_; d++) { s1 += out[d]; s2 = fmaf(out[d], out[d], s2); }
            float m2  = s1 * (1.f / D_);
            float v2  = s2 * (1.f / D_) - m2 * m2;
            float rs2 = rsqrtf(v2 + EPS_);
            float mk  = g_mT[(2 * jp + jj) * B_ + lane];
            cacc += mk;
            #pragma unroll
            for (int d = 0; d < D_; d += 4) {
                float4 gg = *((const float4*)(sg2 + d));
                float4 bb = *((const float4*)(sB2 + d));
                float r0 = fmaxf(fmaf((out[d+0] - m2) * rs2, gg.x, bb.x), 0.f);
                float r1 = fmaxf(fmaf((out[d+1] - m2) * rs2, gg.y, bb.y), 0.f);
                float r2 = fmaxf(fmaf((out[d+2] - m2) * rs2, gg.z, bb.z), 0.f);
                float r3 = fmaxf(fmaf((out[d+3] - m2) * rs2, gg.w, bb.w), 0.f);
                acc[d+0] = fmaf(mk, r0, acc[d+0]);
                acc[d+1] = fmaf(mk, r1, acc[d+1]);
                acc[d+2] = fmaf(mk, r2, acc[d+2]);
                acc[d+3] = fmaf(mk, r3, acc[d+3]);
            }
        }
        __syncwarp();
    }

    // ---- block-level tree reduction (8 warps -> 1), deterministic ----
    #pragma unroll
    for (int half = 4; half >= 1; half >>= 1) {
        if (w >= half && w < 2 * half) {
            float* dst = &sred[w - half][lane][0];
            #pragma unroll
            for (int d = 0; d < D_; d++) dst[d] = acc[d];
        }
        __syncthreads();
        if (w < half) {
            const float* src = &sred[w][lane][0];
            #pragma unroll
            for (int d = 0; d < D_; d++) acc[d] += src[d];
        }
        __syncthreads();
    }

    scnt[w][lane] = cacc;
    __syncthreads();

    if (w == 0) {
        float* dst = g_part + blockIdx.x * (B_ * D_) + lane * D_;
        #pragma unroll
        for (int d = 0; d < D_; d += 4) {
            float4 v; v.x = acc[d]; v.y = acc[d+1]; v.z = acc[d+2]; v.w = acc[d+3];
            *((float4*)(dst + d)) = v;
        }
        float c = 0.f;
        #pragma unroll
        for (int i = 0; i < KB_WARPS; i++) c += scnt[i][lane];
        g_cnt[blockIdx.x * B_ + lane] = c;
    }
}

// ============================================================
// Kernel 3: reduce block partials, mean-pool, encoder MLP, write out.
// ============================================================
__device__ __forceinline__ float block_reduce256(float v, float* red, int t) {
    red[t] = v; __syncthreads();
    #pragma unroll
    for (int s = 128; s > 0; s >>= 1) {
        if (t < s) red[t] += red[t + s];
        __syncthreads();
    }
    float r = red[0]; __syncthreads();
    return r;
}

__global__ __launch_bounds__(256) void k_final(
    const float* __restrict__ eW1, const float* __restrict__ eb1,
    const float* __restrict__ eg1, const float* __restrict__ eB1,
    const float* __restrict__ eW2, const float* __restrict__ eb2,
    const float* __restrict__ eg2, const float* __restrict__ eB2,
    float* __restrict__ out)
{
    int b = blockIdx.x, t = threadIdx.x;
    __shared__ float red[256];
    __shared__ float sc[D_];
    __shared__ float se[EH_];
    __shared__ float sml[64];
    __shared__ float sgp[8][D_];

    float cm = 0.f;
    for (int blk = t; blk < KB_BLOCKS; blk += 256) cm += g_cnt[blk * B_ + b];
    float cnt = block_reduce256(cm, red, t);

    int d = t & 31, g = t >> 5;
    float ps = 0.f;
    for (int blk = g; blk < KB_BLOCKS; blk += 8) ps += g_part[blk * (B_ * D_) + b * D_ + d];
    sgp[g][d] = ps;
    __syncthreads();
    if (t < D_) {
        float s = 0.f;
        #pragma unroll
        for (int gg = 0; gg < 8; gg++) s += sgp[gg][t];
        sc[t] = s / fmaxf(cnt, 1.f);
    }
    __syncthreads();

    float pe = eb1[t];
    #pragma unroll
    for (int k = 0; k < D_; k++) pe = fmaf(sc[k], eW1[k * EH_ + t], pe);
    float s1 = block_reduce256(pe, red, t);
    float s2 = block_reduce256(pe * pe, red, t);
    float m  = s1 * (1.f / EH_);
    float v  = s2 * (1.f / EH_) - m * m;
    float rs = rsqrtf(v + EPS_);
    se[t] = fmaxf(fmaf((pe - m) * rs, eg1[t], eB1[t]), 0.f);
    __syncthreads();

    if (t < 64) {
        float pm = eb2[t];
        for (int k = 0; k < EH_; k++) pm = fmaf(se[k], eW2[k * 64 + t], pm);
        sml[t] = pm;
    }
    __syncthreads();
    if (t < 64) {
        float a = 0.f, q = 0.f;
        #pragma unroll
        for (int k = 0; k < 64; k++) { a += sml[k]; q = fmaf(sml[k], sml[k], q); }
        float mm = a * (1.f / 64.f);
        float vv = q * (1.f / 64.f) - mm * mm;
        float rr = rsqrtf(vv + EPS_);
        float ml = fmaxf(fmaf((sml[t] - mm) * rr, eg2[t], eB2[t]), 0.f);
        int off = (t < 32) ? (b * 32 + t) : (B_ * 32 + b * 32 + (t - 32));
        out[off] = ml;
    }
}

// ============================================================
extern "C" void kernel_launch(void* const* d_in, const int* in_sizes, int n_in,
                              void* d_out, int out_size) {
    const float* x         = (const float*)d_in[0];
    const int*   mask      = (const int*)  d_in[1];
    const int*   atse_idx  = (const int*)  d_in[2];
    const float* feat_emb  = (const float*)d_in[3];
    const float* atse_emb  = (const float*)d_in[4];
    const float* hW1       = (const float*)d_in[5];
    const float* hb1       = (const float*)d_in[6];
    const float* hg1       = (const float*)d_in[7];
    // d_in[8] = hB1
    const float* hB1       = (const float*)d_in[8];
    const float* hW2       = (const float*)d_in[9];
    const float* hb2       = (const float*)d_in[10];
    const float* hg2       = (const float*)d_in[11];
    const float* hB2       = (const float*)d_in[12];
    const float* eW1       = (const float*)d_in[13];
    const float* eb1       = (const float*)d_in[14];
    const float* eg1       = (const float*)d_in[15];
    const float* eB1       = (const float*)d_in[16];
    const float* eW2       = (const float*)d_in[17];
    const float* eb2       = (const float*)d_in[18];
    const float* eg2       = (const float*)d_in[19];
    const float* eB2       = (const float*)d_in[20];
    float* out = (float*)d_out;

    k_prep0<<<1, 128>>>(hW1, hg1, hB1);
    k_xpose<<<J_ / 32, 256>>>(x, mask);
    k_pre<<<J_ / 32, 128>>>(feat_emb, atse_emb, atse_idx, hW1, hb1, hg1);
    k_main<<<KB_BLOCKS, 256>>>(hW2, hb2, hg2, hB2);
    k_final<<<B_, 256>>>(eW1, eb1, eg1, eB1, eW2, eb2, eg2, eB2, out);
}